// round 7
// baseline (speedup 1.0000x reference)
#include <cuda_runtime.h>
#include <cuda_bf16.h>
#include <cstdint>
#include <cmath>

typedef unsigned long long ull;

#define NB   8
#define NI   8192
#define IDIM 180
#define ADIM 1536
#define SDIM 1536
#define NS   64

// ----------------------------- device scratch -------------------------------
__device__ float g_Mpart[4 * IDIM * ADIM];
__device__ float g_M[IDIM * ADIM];
__device__ float g_Tpart[64 * IDIM * NS];
__device__ float g_Tt[NB * NS * IDIM];
__device__ float g_Gpart[64 * NS * NS];
__device__ float g_G[NB * NS * NS];
__device__ float g_m[NB * NS];
__device__ float g_stats[2 * NB * NI];
__device__ __align__(16) __nv_bfloat16 g_sThi[NB * SDIM * NS];   // slots^T hi [b][d][s]
__device__ __align__(16) __nv_bfloat16 g_sTlo[NB * SDIM * NS];   // slots^T lo
__device__ __align__(16) __nv_bfloat16 g_whi[NB * NI * NS];      // w hi [b][i][s]
__device__ __align__(16) __nv_bfloat16 g_wlo[NB * NI * NS];      // w lo

// ----------------------------- warp helpers ---------------------------------
__device__ __forceinline__ float wsum(float v) {
    #pragma unroll
    for (int o = 16; o > 0; o >>= 1) v += __shfl_xor_sync(0xffffffffu, v, o);
    return v;
}
__device__ __forceinline__ float wmax(float v) {
    #pragma unroll
    for (int o = 16; o > 0; o >>= 1) v = fmaxf(v, __shfl_xor_sync(0xffffffffu, v, o));
    return v;
}
__device__ __forceinline__ uint32_t smem_u32(const void* p) {
    uint32_t a;
    asm("{ .reg .u64 t; cvta.to.shared.u64 t, %1; cvt.u32.u64 %0, t; }" : "=r"(a) : "l"(p));
    return a;
}

// --------------------------- mma.sync helpers --------------------------------
__device__ __forceinline__ void ldm_x4(uint32_t a, uint32_t* r) {
    asm volatile("ldmatrix.sync.aligned.m8n8.x4.shared.b16 {%0,%1,%2,%3}, [%4];"
        : "=r"(r[0]), "=r"(r[1]), "=r"(r[2]), "=r"(r[3]) : "r"(a));
}
__device__ __forceinline__ void mma_bf16(float* c, const uint32_t* a, const uint32_t* b) {
    asm volatile("mma.sync.aligned.m16n8k16.row.col.f32.bf16.bf16.f32 "
        "{%0,%1,%2,%3}, {%4,%5,%6,%7}, {%8,%9}, {%0,%1,%2,%3};"
        : "+f"(c[0]), "+f"(c[1]), "+f"(c[2]), "+f"(c[3])
        : "r"(a[0]), "r"(a[1]), "r"(a[2]), "r"(a[3]), "r"(b[0]), "r"(b[1]));
}

// ----------------------- generic NT GEMM, split-K partials ------------------
__global__ void __launch_bounds__(256) gemm_nt(
    const float* __restrict__ A, const float* __restrict__ B, float* __restrict__ Cp,
    int M, int N, int Kchunk, int lda, int ldb,
    long long aBS, long long bBS, int nsplit)
{
    int z = blockIdx.z;
    int kk = z % nsplit;
    int batch = z / nsplit;
    A += (long long)batch * aBS + (long long)kk * Kchunk;
    B += (long long)batch * bBS + (long long)kk * Kchunk;
    Cp += (long long)z * M * N;

    int m0 = blockIdx.x * 64, n0 = blockIdx.y * 64;
    __shared__ __align__(16) float As[16][68];
    __shared__ __align__(16) float Bs[16][68];

    int tid = threadIdx.x;
    int tr = tid >> 4, tc = tid & 15;
    int lr = tid >> 2, lq = tid & 3;

    float acc[4][4] = {};

    for (int kb = 0; kb < Kchunk; kb += 16) {
        __syncthreads();
        float4 av = make_float4(0.f, 0.f, 0.f, 0.f);
        if (m0 + lr < M)
            av = *(const float4*)&A[(long long)(m0 + lr) * lda + kb + 4 * lq];
        As[4 * lq + 0][lr] = av.x; As[4 * lq + 1][lr] = av.y;
        As[4 * lq + 2][lr] = av.z; As[4 * lq + 3][lr] = av.w;
        float4 bv = make_float4(0.f, 0.f, 0.f, 0.f);
        if (n0 + lr < N)
            bv = *(const float4*)&B[(long long)(n0 + lr) * ldb + kb + 4 * lq];
        Bs[4 * lq + 0][lr] = bv.x; Bs[4 * lq + 1][lr] = bv.y;
        Bs[4 * lq + 2][lr] = bv.z; Bs[4 * lq + 3][lr] = bv.w;
        __syncthreads();
        #pragma unroll
        for (int k = 0; k < 16; ++k) {
            float4 a4 = *(const float4*)&As[k][4 * tr];
            float4 b4 = *(const float4*)&Bs[k][4 * tc];
            float a[4] = {a4.x, a4.y, a4.z, a4.w};
            float b[4] = {b4.x, b4.y, b4.z, b4.w};
            #pragma unroll
            for (int i = 0; i < 4; ++i)
                #pragma unroll
                for (int j = 0; j < 4; ++j)
                    acc[i][j] = fmaf(a[i], b[j], acc[i][j]);
        }
    }
    #pragma unroll
    for (int i = 0; i < 4; ++i)
        #pragma unroll
        for (int j = 0; j < 4; ++j) {
            int m = m0 + 4 * tr + i, n = n0 + 4 * tc + j;
            if (m < M && n < N) Cp[(long long)m * N + n] = acc[i][j];
        }
}

// -------------------------- split-K reduce for M ----------------------------
__global__ void reduce_bt(const float* __restrict__ part, float* __restrict__ out,
                          int nper, int nparts)
{
    int b = blockIdx.y;
    int i = blockIdx.x * 256 + threadIdx.x;
    if (i >= nper) return;
    const float* p = part + (long long)b * nparts * nper + i;
    float s = 0.f;
    for (int k = 0; k < nparts; ++k) s += p[(long long)k * nper];
    out[(long long)b * nper + i] = s;
}

// ---------------- fused finisher: reduce_G + reduce_T + means + split -------
// blockIdx.x ranges: [0,128) reduce G, [128,488) reduce T,
//                    [488,496) slot means, [496,592) split slots
__global__ void __launch_bounds__(256) prep_finish(const float* __restrict__ slots,
                                                   float scale)
{
    __shared__ float ts[64][129];
    int bx = blockIdx.x;
    int tid = threadIdx.x;

    if (bx < 128) {                       // reduce G
        int idx = bx * 256 + tid;         // over 8 * 4096
        int b = idx >> 12, r = idx & 4095;
        const float* p = g_Gpart + ((long long)b * 8) * (NS * NS) + r;
        float s = 0.f;
        #pragma unroll
        for (int k = 0; k < 8; ++k) s += p[(long long)k * (NS * NS)];
        g_G[(long long)b * (NS * NS) + r] = s;
    } else if (bx < 488) {                // reduce T (+ scale + transpose)
        int idx = (bx - 128) * 256 + tid; // over 8 * 11520
        if (idx < 8 * IDIM * NS) {
            int b = idx / (IDIM * NS);
            int i = idx % (IDIM * NS);
            int s = i / IDIM, d = i % IDIM;
            const float* p = g_Tpart + ((long long)b * 8) * (IDIM * NS) + d * NS + s;
            float acc = 0.f;
            #pragma unroll
            for (int k = 0; k < 8; ++k) acc += p[(long long)k * (IDIM * NS)];
            g_Tt[(long long)b * (NS * IDIM) + i] = acc * scale;
        }
    } else if (bx < 496) {                // slot means
        int b = bx - 488;
        int warp = tid >> 5, lane = tid & 31;
        for (int s = warp; s < NS; s += 8) {
            const float* r = slots + ((long long)b * NS + s) * SDIM;
            float acc = 0.f;
            for (int d = lane; d < SDIM; d += 32) acc += r[d];
            acc = wsum(acc);
            if (lane == 0) g_m[b * NS + s] = acc * (1.0f / SDIM);
        }
    } else {                              // split slots -> sT hi/lo
        int jd = bx - 496;
        int b = jd / 12;
        int d0 = (jd % 12) * 128;
        for (int idx = tid; idx < 64 * 128; idx += 256) {
            int s = idx >> 7, dd = idx & 127;
            ts[s][dd] = slots[((long long)b * NS + s) * SDIM + d0 + dd];
        }
        __syncthreads();
        for (int idx = tid; idx < 128 * 64; idx += 256) {
            int d = idx >> 6, s = idx & 63;
            float v = ts[s][d];
            __nv_bfloat16 h = __float2bfloat16(v);
            __nv_bfloat16 l = __float2bfloat16(v - __bfloat162float(h));
            long long o = ((long long)b * SDIM + d0 + d) * NS + s;
            g_sThi[o] = h;
            g_sTlo[o] = l;
        }
    }
}

// ----------------- dots + softmax + LN2-stats fused kernel ------------------
#define D_TT   0            // 64 x 188
#define D_G    12032        // 64 x 65
#define D_M    16192        // 64
#define D_G1   16256        // 184
#define D_B1   16440        // 184
#define D_XN   16624        // 8 warps x 4 rows x 184
#define D_W    22512        // 8 warps x 4 rows x 64
#define DOTS_SMEM_FLOATS 24560
#define DOTS_SMEM_BYTES  (DOTS_SMEM_FLOATS * 4)

__global__ void __launch_bounds__(256) dots_kernel(
    const float* __restrict__ x, const float* __restrict__ g1v,
    const float* __restrict__ b1v, float* __restrict__ out_w)
{
    extern __shared__ float sm[];
    int tid = threadIdx.x;
    int b = blockIdx.y;

    for (int i = tid; i < IDIM * NS; i += 256) {
        int s = i / IDIM, d = i % IDIM;
        sm[D_TT + s * 188 + d] = g_Tt[(long long)b * (NS * IDIM) + i];
    }
    for (int i = tid; i < NS * NS; i += 256) {
        int s = i >> 6, c = i & 63;
        sm[D_G + s * 65 + c] = g_G[(long long)b * (NS * NS) + i];
    }
    if (tid < NS) sm[D_M + tid] = g_m[b * NS + tid];
    if (tid < IDIM) { sm[D_G1 + tid] = g1v[tid]; sm[D_B1 + tid] = b1v[tid]; }
    __syncthreads();

    int warp = tid >> 5, lane = tid & 31;
    long long rowbase = (long long)blockIdx.x * 32 + warp * 4;
    long long gbase = (long long)b * NI + rowbase;
    float* xnW = sm + D_XN + warp * (4 * 184);
    float* wW  = sm + D_W  + warp * (4 * 64);

    #pragma unroll
    for (int j = 0; j < 4; ++j) {
        const float* xr = x + (gbase + j) * IDIM;
        float xv[6];
        float s1 = 0.f, s2 = 0.f;
        #pragma unroll
        for (int t = 0; t < 6; ++t) {
            int d = lane + 32 * t;
            float v = (d < IDIM) ? xr[d] : 0.f;
            xv[t] = v; s1 += v; s2 = fmaf(v, v, s2);
        }
        s1 = wsum(s1); s2 = wsum(s2);
        float mu = s1 * (1.0f / IDIM);
        float rs = rsqrtf(s2 * (1.0f / IDIM) - mu * mu + 1e-5f);
        #pragma unroll
        for (int t = 0; t < 6; ++t) {
            int d = lane + 32 * t;
            if (d < IDIM)
                xnW[j * 184 + d] = (xv[t] - mu) * rs * sm[D_G1 + d] + sm[D_B1 + d];
        }
    }
    __syncwarp();

    float a0[4] = {0.f, 0.f, 0.f, 0.f}, a1[4] = {0.f, 0.f, 0.f, 0.f};
    const float* t0p = sm + D_TT + lane * 188;
    const float* t1p = t0p + 32 * 188;
    #pragma unroll 3
    for (int d4 = 0; d4 < IDIM; d4 += 4) {
        float4 t0 = *(const float4*)(t0p + d4);
        float4 t1 = *(const float4*)(t1p + d4);
        #pragma unroll
        for (int j = 0; j < 4; ++j) {
            float4 xv = *(const float4*)(xnW + j * 184 + d4);
            a0[j] = fmaf(xv.x, t0.x, fmaf(xv.y, t0.y, fmaf(xv.z, t0.z, fmaf(xv.w, t0.w, a0[j]))));
            a1[j] = fmaf(xv.x, t1.x, fmaf(xv.y, t1.y, fmaf(xv.z, t1.z, fmaf(xv.w, t1.w, a1[j]))));
        }
    }

    float w1a[4], w2a[4], mu2a[4];
    #pragma unroll
    for (int j = 0; j < 4; ++j) {
        float mx = wmax(fmaxf(a0[j], a1[j]));
        float e1 = __expf(a0[j] - mx), e2 = __expf(a1[j] - mx);
        float sum = wsum(e1 + e2);
        float inv = 1.0f / sum;
        float w1 = e1 * inv, w2 = e2 * inv;
        float* wo = out_w + (gbase + j) * NS;
        wo[lane] = w1; wo[lane + 32] = w2;
        __nv_bfloat16 h1 = __float2bfloat16(w1);
        __nv_bfloat16 h2 = __float2bfloat16(w2);
        long long wb = (gbase + j) * NS;
        g_whi[wb + lane] = h1;
        g_whi[wb + lane + 32] = h2;
        g_wlo[wb + lane] = __float2bfloat16(w1 - __bfloat162float(h1));
        g_wlo[wb + lane + 32] = __float2bfloat16(w2 - __bfloat162float(h2));
        wW[j * 64 + lane] = w1; wW[j * 64 + lane + 32] = w2;
        w1a[j] = w1; w2a[j] = w2;
        mu2a[j] = wsum(w1 * sm[D_M + lane] + w2 * sm[D_M + lane + 32]);
    }
    __syncwarp();

    const float* gr0 = sm + D_G + lane * 65;
    const float* gr1 = gr0 + 32 * 65;
    #pragma unroll
    for (int j = 0; j < 4; ++j) {
        float gw1 = 0.f, gw2 = 0.f;
        #pragma unroll 4
        for (int sp = 0; sp < NS; ++sp) {
            float ws = wW[j * 64 + sp];
            gw1 = fmaf(gr0[sp], ws, gw1);
            gw2 = fmaf(gr1[sp], ws, gw2);
        }
        float ssq = wsum(w1a[j] * gw1 + w2a[j] * gw2);
        float mu2 = mu2a[j];
        float rs2 = rsqrtf(ssq * (1.0f / SDIM) - mu2 * mu2 + 1e-5f);
        if (lane == 0) {
            g_stats[gbase + j] = mu2;
            g_stats[(long long)NB * NI + gbase + j] = rs2;
        }
    }
}

// ---------- mma.sync output GEMM v2: persistent w, loop d-tiles -------------
// CTA = 128 i-rows x batch; loops 12 d-tiles of 128 with double-buffered sT.
#define OW_HI   0
#define OW_LO   18432
#define OS_BUF0 36864       // hi at +0, lo at +18432 within buffer
#define OS_BUF1 73728
#define O_STATS 110592      // mu[128], rs[128]
#define OUT2_BYTES 111616

__global__ void __launch_bounds__(256, 2) out_mma2_kernel(
    const float* __restrict__ g2v, const float* __restrict__ b2v,
    float* __restrict__ out_s)
{
    extern __shared__ char smc[];
    int tid = threadIdx.x;
    int b = blockIdx.y;
    long long gib = (long long)b * NI + (long long)blockIdx.x * 128;

    // w tile hi/lo -> smem (row pad 144B)
    const uint4* wh = (const uint4*)(g_whi + gib * NS);
    const uint4* wl = (const uint4*)(g_wlo + gib * NS);
    #pragma unroll
    for (int it = 0; it < 4; ++it) {
        int idx = tid + 256 * it;            // 1024 uint4
        uint32_t doff = (uint32_t)(idx >> 3) * 144 + (uint32_t)(idx & 7) * 16;
        *(uint4*)(smc + OW_HI + doff) = wh[idx];
        *(uint4*)(smc + OW_LO + doff) = wl[idx];
    }
    if (tid < 128) {
        ((float*)(smc + O_STATS))[tid]       = g_stats[gib + tid];
        ((float*)(smc + O_STATS + 512))[tid] = g_stats[(long long)NB * NI + gib + tid];
    }

    // preload sT tile 0
    const __nv_bfloat16* sThB = g_sThi + (long long)b * SDIM * NS;
    const __nv_bfloat16* sTlB = g_sTlo + (long long)b * SDIM * NS;
    {
        const uint4* ph = (const uint4*)sThB;
        const uint4* pl = (const uint4*)sTlB;
        #pragma unroll
        for (int it = 0; it < 4; ++it) {
            int idx = tid + 256 * it;
            uint32_t doff = (uint32_t)(idx >> 3) * 144 + (uint32_t)(idx & 7) * 16;
            *(uint4*)(smc + OS_BUF0 + doff) = ph[idx];
            *(uint4*)(smc + OS_BUF0 + 18432 + doff) = pl[idx];
        }
    }

    int wid = tid >> 5, lane = tid & 31;
    int wm = wid & 3, wn = wid >> 2;          // warp tile: 32 i x 64 d
    uint32_t sbase = smem_u32(smc);
    int trow = lane & 15;
    uint32_t tcolb = (uint32_t)(lane >> 4) * 16;
    uint32_t brow = (uint32_t)(wn * 64 + ((lane >> 3) & 1) * 8 + (lane & 7)) * 144;
    const float* muP = (const float*)(smc + O_STATS);
    const float* rsP = (const float*)(smc + O_STATS + 512);
    int grp = lane >> 2, tig = lane & 3;

    for (int t = 0; t < 12; ++t) {
        __syncthreads();
        uint32_t bufoff = (t & 1) ? OS_BUF1 : OS_BUF0;

        // prefetch next sT tile into registers (LDG early for latency hiding)
        uint4 pf[8];
        bool dopf = (t + 1 < 12);
        if (dopf) {
            const uint4* ph = (const uint4*)(sThB + (long long)(t + 1) * 128 * NS);
            const uint4* pl = (const uint4*)(sTlB + (long long)(t + 1) * 128 * NS);
            #pragma unroll
            for (int e = 0; e < 4; ++e) {
                pf[e]     = ph[tid + 256 * e];
                pf[4 + e] = pl[tid + 256 * e];
            }
        }

        // mma: 3-term bf16 split
        float c[2][8][4];
        #pragma unroll
        for (int mi = 0; mi < 2; ++mi)
            #pragma unroll
            for (int nj = 0; nj < 8; ++nj)
                #pragma unroll
                for (int q = 0; q < 4; ++q) c[mi][nj][q] = 0.f;

        #pragma unroll
        for (int ks = 0; ks < 4; ++ks) {
            uint32_t kb = (uint32_t)ks * 32 + tcolb;
            uint32_t ah[2][4], al[2][4];
            #pragma unroll
            for (int mi = 0; mi < 2; ++mi) {
                uint32_t ra = sbase + OW_HI + (uint32_t)(wm * 32 + mi * 16 + trow) * 144 + kb;
                ldm_x4(ra, ah[mi]);
                ldm_x4(ra + (OW_LO - OW_HI), al[mi]);
            }
            #pragma unroll
            for (int g = 0; g < 4; ++g) {
                uint32_t rb = sbase + bufoff + brow + (uint32_t)(g * 16) * 144 + kb;
                uint32_t th[4], tl[4];
                ldm_x4(rb, th);
                ldm_x4(rb + 18432, tl);
                uint32_t bh0[2] = {th[0], th[2]}, bh1[2] = {th[1], th[3]};
                uint32_t bl0[2] = {tl[0], tl[2]}, bl1[2] = {tl[1], tl[3]};
                #pragma unroll
                for (int mi = 0; mi < 2; ++mi) {
                    mma_bf16(c[mi][2 * g],     ah[mi], bh0);
                    mma_bf16(c[mi][2 * g],     ah[mi], bl0);
                    mma_bf16(c[mi][2 * g],     al[mi], bh0);
                    mma_bf16(c[mi][2 * g + 1], ah[mi], bh1);
                    mma_bf16(c[mi][2 * g + 1], ah[mi], bl1);
                    mma_bf16(c[mi][2 * g + 1], al[mi], bh1);
                }
            }
        }

        // store prefetched tile into the other buffer
        if (dopf) {
            uint32_t obuf = (t & 1) ? OS_BUF0 : OS_BUF1;
            #pragma unroll
            for (int e = 0; e < 4; ++e) {
                int idx = tid + 256 * e;
                uint32_t doff = (uint32_t)(idx >> 3) * 144 + (uint32_t)(idx & 7) * 16;
                *(uint4*)(smc + obuf + doff) = pf[e];
                *(uint4*)(smc + obuf + 18432 + doff) = pf[4 + e];
            }
        }

        // epilogue: LN + store
        int d0 = t * 128;
        #pragma unroll
        for (int mi = 0; mi < 2; ++mi) {
            int r0 = wm * 32 + mi * 16 + grp;
            int r1 = r0 + 8;
            float mu0 = muP[r0], rs0 = rsP[r0];
            float mu1 = muP[r1], rs1 = rsP[r1];
            #pragma unroll
            for (int nj = 0; nj < 8; ++nj) {
                int col = d0 + wn * 64 + nj * 8 + 2 * tig;
                float2 gm = *(const float2*)(g2v + col);
                float2 bt = *(const float2*)(b2v + col);
                float* c4 = c[mi][nj];
                float2 v0, v1;
                v0.x = (c4[0] - mu0) * rs0 * gm.x + bt.x;
                v0.y = (c4[1] - mu0) * rs0 * gm.y + bt.y;
                v1.x = (c4[2] - mu1) * rs1 * gm.x + bt.x;
                v1.y = (c4[3] - mu1) * rs1 * gm.y + bt.y;
                *(float2*)(out_s + (gib + r0) * (long long)SDIM + col) = v0;
                *(float2*)(out_s + (gib + r1) * (long long)SDIM + col) = v1;
            }
        }
    }
}

// ------------------------------- launcher -----------------------------------
extern "C" void kernel_launch(void* const* d_in, const int* in_sizes, int n_in,
                              void* d_out, int out_size)
{
    const float* x     = (const float*)d_in[0];
    const float* slots = (const float*)d_in[1];
    const float* Wq    = (const float*)d_in[2];
    const float* Wk    = (const float*)d_in[3];
    const float* g1v   = (const float*)d_in[4];
    const float* b1v   = (const float*)d_in[5];
    const float* g2v   = (const float*)d_in[6];
    const float* b2v   = (const float*)d_in[7];

    float* out_s = (float*)d_out;
    float* out_w = out_s + (long long)NB * NI * SDIM;

    float *pMpart, *pM, *pTpart, *pGpart;
    cudaGetSymbolAddress((void**)&pMpart, g_Mpart);
    cudaGetSymbolAddress((void**)&pM,     g_M);
    cudaGetSymbolAddress((void**)&pTpart, g_Tpart);
    cudaGetSymbolAddress((void**)&pGpart, g_Gpart);

    cudaFuncSetAttribute(dots_kernel, cudaFuncAttributeMaxDynamicSharedMemorySize, DOTS_SMEM_BYTES);
    cudaFuncSetAttribute(out_mma2_kernel, cudaFuncAttributeMaxDynamicSharedMemorySize, OUT2_BYTES);

    float scale = (float)(1.0 / sqrt((double)ADIM));

    // 1) M = Wq @ Wk^T (180 x 1536), split-K x4
    gemm_nt<<<dim3(3, 24, 4), 256>>>(Wq, Wk, pMpart, IDIM, ADIM, ADIM / 4,
                                     ADIM, ADIM, 0LL, 0LL, 4);
    // 2) reduce M
    reduce_bt<<<dim3((IDIM * ADIM + 255) / 256, 1), 256>>>(pMpart, pM, IDIM * ADIM, 4);
    // 3) T[b] = M @ slots[b]^T, split-K x8
    gemm_nt<<<dim3(3, 1, 64), 256>>>(pM, slots, pTpart, IDIM, NS, SDIM / 8,
                                     ADIM, SDIM, 0LL, (long long)NS * SDIM, 8);
    // 4) G[b] = slots slots^T, split-K x8
    gemm_nt<<<dim3(1, 1, 64), 256>>>(slots, slots, pGpart, NS, NS, SDIM / 8,
                                     SDIM, SDIM, (long long)NS * SDIM, (long long)NS * SDIM, 8);
    // 5) fused finishers: reduce G, reduce+scale+transpose T, slot means, split slots
    prep_finish<<<592, 256>>>(slots, scale);
    // 6) dots + softmax + LN2 stats (+ w bf16 hi/lo)
    dots_kernel<<<dim3(NI / 32, NB), 256, DOTS_SMEM_BYTES>>>(x, g1v, b1v, out_w);
    // 7) output GEMM + LN epilogue
    out_mma2_kernel<<<dim3(NI / 128, NB), 256, OUT2_BYTES>>>(g2v, b2v, out_s);
}

// round 8
// speedup vs baseline: 1.1885x; 1.1885x over previous
#include <cuda_runtime.h>
#include <cuda_bf16.h>
#include <cstdint>
#include <cmath>

typedef unsigned long long ull;

#define NB   8
#define NI   8192
#define IDIM 180
#define ADIM 1536
#define SDIM 1536
#define NS   64

// ----------------------------- device scratch -------------------------------
__device__ float g_Mpart[8 * IDIM * ADIM];
__device__ float g_M[IDIM * ADIM];
__device__ float g_Tpart[128 * IDIM * NS];
__device__ float g_Tt[NB * NS * IDIM];
__device__ float g_Gpart[128 * NS * NS];
__device__ float g_G[NB * NS * NS];
__device__ float g_m[NB * NS];
__device__ float g_stats[2 * NB * NI];
__device__ __align__(16) __nv_bfloat16 g_sThi[NB * SDIM * NS];   // slots^T hi [b][d][s]
__device__ __align__(16) __nv_bfloat16 g_sTlo[NB * SDIM * NS];   // slots^T lo
__device__ __align__(16) __nv_bfloat16 g_whi[NB * NI * NS];      // w hi [b][i][s]
__device__ __align__(16) __nv_bfloat16 g_wlo[NB * NI * NS];      // w lo

// ----------------------------- warp helpers ---------------------------------
__device__ __forceinline__ float wsum(float v) {
    #pragma unroll
    for (int o = 16; o > 0; o >>= 1) v += __shfl_xor_sync(0xffffffffu, v, o);
    return v;
}
__device__ __forceinline__ float wmax(float v) {
    #pragma unroll
    for (int o = 16; o > 0; o >>= 1) v = fmaxf(v, __shfl_xor_sync(0xffffffffu, v, o));
    return v;
}
__device__ __forceinline__ uint32_t smem_u32(const void* p) {
    uint32_t a;
    asm("{ .reg .u64 t; cvta.to.shared.u64 t, %1; cvt.u32.u64 %0, t; }" : "=r"(a) : "l"(p));
    return a;
}

// --------------------------- mma.sync helpers --------------------------------
__device__ __forceinline__ void ldm_x4(uint32_t a, uint32_t* r) {
    asm volatile("ldmatrix.sync.aligned.m8n8.x4.shared.b16 {%0,%1,%2,%3}, [%4];"
        : "=r"(r[0]), "=r"(r[1]), "=r"(r[2]), "=r"(r[3]) : "r"(a));
}
__device__ __forceinline__ void mma_bf16(float* c, const uint32_t* a, const uint32_t* b) {
    asm volatile("mma.sync.aligned.m16n8k16.row.col.f32.bf16.bf16.f32 "
        "{%0,%1,%2,%3}, {%4,%5,%6,%7}, {%8,%9}, {%0,%1,%2,%3};"
        : "+f"(c[0]), "+f"(c[1]), "+f"(c[2]), "+f"(c[3])
        : "r"(a[0]), "r"(a[1]), "r"(a[2]), "r"(a[3]), "r"(b[0]), "r"(b[1]));
}

// ----------------------- generic NT GEMM, split-K partials ------------------
__global__ void __launch_bounds__(256) gemm_nt(
    const float* __restrict__ A, const float* __restrict__ B, float* __restrict__ Cp,
    int M, int N, int Kchunk, int lda, int ldb,
    long long aBS, long long bBS, int nsplit)
{
    int z = blockIdx.z;
    int kk = z % nsplit;
    int batch = z / nsplit;
    A += (long long)batch * aBS + (long long)kk * Kchunk;
    B += (long long)batch * bBS + (long long)kk * Kchunk;
    Cp += (long long)z * M * N;

    int m0 = blockIdx.x * 64, n0 = blockIdx.y * 64;
    __shared__ __align__(16) float As[16][68];
    __shared__ __align__(16) float Bs[16][68];

    int tid = threadIdx.x;
    int tr = tid >> 4, tc = tid & 15;
    int lr = tid >> 2, lq = tid & 3;

    float acc[4][4] = {};

    for (int kb = 0; kb < Kchunk; kb += 16) {
        __syncthreads();
        float4 av = make_float4(0.f, 0.f, 0.f, 0.f);
        if (m0 + lr < M)
            av = *(const float4*)&A[(long long)(m0 + lr) * lda + kb + 4 * lq];
        As[4 * lq + 0][lr] = av.x; As[4 * lq + 1][lr] = av.y;
        As[4 * lq + 2][lr] = av.z; As[4 * lq + 3][lr] = av.w;
        float4 bv = make_float4(0.f, 0.f, 0.f, 0.f);
        if (n0 + lr < N)
            bv = *(const float4*)&B[(long long)(n0 + lr) * ldb + kb + 4 * lq];
        Bs[4 * lq + 0][lr] = bv.x; Bs[4 * lq + 1][lr] = bv.y;
        Bs[4 * lq + 2][lr] = bv.z; Bs[4 * lq + 3][lr] = bv.w;
        __syncthreads();
        #pragma unroll
        for (int k = 0; k < 16; ++k) {
            float4 a4 = *(const float4*)&As[k][4 * tr];
            float4 b4 = *(const float4*)&Bs[k][4 * tc];
            float a[4] = {a4.x, a4.y, a4.z, a4.w};
            float b[4] = {b4.x, b4.y, b4.z, b4.w};
            #pragma unroll
            for (int i = 0; i < 4; ++i)
                #pragma unroll
                for (int j = 0; j < 4; ++j)
                    acc[i][j] = fmaf(a[i], b[j], acc[i][j]);
        }
    }
    #pragma unroll
    for (int i = 0; i < 4; ++i)
        #pragma unroll
        for (int j = 0; j < 4; ++j) {
            int m = m0 + 4 * tr + i, n = n0 + 4 * tc + j;
            if (m < M && n < N) Cp[(long long)m * N + n] = acc[i][j];
        }
}

// -------------------------- split-K reduce for M ----------------------------
__global__ void reduce_bt(const float* __restrict__ part, float* __restrict__ out,
                          int nper, int nparts)
{
    int b = blockIdx.y;
    int i = blockIdx.x * 256 + threadIdx.x;
    if (i >= nper) return;
    const float* p = part + (long long)b * nparts * nper + i;
    float s = 0.f;
    for (int k = 0; k < nparts; ++k) s += p[(long long)k * nper];
    out[(long long)b * nper + i] = s;
}

// ---------------- fused finisher: reduce_G + reduce_T + means + split -------
// blockIdx.x ranges: [0,128) reduce G, [128,488) reduce T,
//                    [488,496) slot means, [496,592) split slots
__global__ void __launch_bounds__(256) prep_finish(const float* __restrict__ slots,
                                                   float scale)
{
    __shared__ float ts[64][129];
    int bx = blockIdx.x;
    int tid = threadIdx.x;

    if (bx < 128) {                       // reduce G (16 parts per batch)
        int idx = bx * 256 + tid;         // over 8 * 4096
        int b = idx >> 12, r = idx & 4095;
        const float* p = g_Gpart + ((long long)b * 16) * (NS * NS) + r;
        float s = 0.f;
        #pragma unroll
        for (int k = 0; k < 16; ++k) s += p[(long long)k * (NS * NS)];
        g_G[(long long)b * (NS * NS) + r] = s;
    } else if (bx < 488) {                // reduce T (16 parts; + scale + transpose)
        int idx = (bx - 128) * 256 + tid; // over 8 * 11520
        if (idx < 8 * IDIM * NS) {
            int b = idx / (IDIM * NS);
            int i = idx % (IDIM * NS);
            int s = i / IDIM, d = i % IDIM;
            const float* p = g_Tpart + ((long long)b * 16) * (IDIM * NS) + d * NS + s;
            float acc = 0.f;
            #pragma unroll
            for (int k = 0; k < 16; ++k) acc += p[(long long)k * (IDIM * NS)];
            g_Tt[(long long)b * (NS * IDIM) + i] = acc * scale;
        }
    } else if (bx < 496) {                // slot means
        int b = bx - 488;
        int warp = tid >> 5, lane = tid & 31;
        for (int s = warp; s < NS; s += 8) {
            const float* r = slots + ((long long)b * NS + s) * SDIM;
            float acc = 0.f;
            for (int d = lane; d < SDIM; d += 32) acc += r[d];
            acc = wsum(acc);
            if (lane == 0) g_m[b * NS + s] = acc * (1.0f / SDIM);
        }
    } else {                              // split slots -> sT hi/lo
        int jd = bx - 496;
        int b = jd / 12;
        int d0 = (jd % 12) * 128;
        for (int idx = tid; idx < 64 * 128; idx += 256) {
            int s = idx >> 7, dd = idx & 127;
            ts[s][dd] = slots[((long long)b * NS + s) * SDIM + d0 + dd];
        }
        __syncthreads();
        for (int idx = tid; idx < 128 * 64; idx += 256) {
            int d = idx >> 6, s = idx & 63;
            float v = ts[s][d];
            __nv_bfloat16 h = __float2bfloat16(v);
            __nv_bfloat16 l = __float2bfloat16(v - __bfloat162float(h));
            long long o = ((long long)b * SDIM + d0 + d) * NS + s;
            g_sThi[o] = h;
            g_sTlo[o] = l;
        }
    }
}

// ----------------- dots + softmax + LN2-stats fused kernel ------------------
#define D_TT   0            // 64 x 188
#define D_G    12032        // 64 x 65
#define D_M    16192        // 64
#define D_G1   16256        // 184
#define D_B1   16440        // 184
#define D_XN   16624        // 8 warps x 4 rows x 184
#define D_W    22512        // 8 warps x 4 rows x 64
#define DOTS_SMEM_FLOATS 24560
#define DOTS_SMEM_BYTES  (DOTS_SMEM_FLOATS * 4)

__global__ void __launch_bounds__(256) dots_kernel(
    const float* __restrict__ x, const float* __restrict__ g1v,
    const float* __restrict__ b1v, float* __restrict__ out_w)
{
    extern __shared__ float sm[];
    int tid = threadIdx.x;
    int b = blockIdx.y;

    for (int i = tid; i < IDIM * NS; i += 256) {
        int s = i / IDIM, d = i % IDIM;
        sm[D_TT + s * 188 + d] = g_Tt[(long long)b * (NS * IDIM) + i];
    }
    for (int i = tid; i < NS * NS; i += 256) {
        int s = i >> 6, c = i & 63;
        sm[D_G + s * 65 + c] = g_G[(long long)b * (NS * NS) + i];
    }
    if (tid < NS) sm[D_M + tid] = g_m[b * NS + tid];
    if (tid < IDIM) { sm[D_G1 + tid] = g1v[tid]; sm[D_B1 + tid] = b1v[tid]; }
    __syncthreads();

    int warp = tid >> 5, lane = tid & 31;
    long long rowbase = (long long)blockIdx.x * 32 + warp * 4;
    long long gbase = (long long)b * NI + rowbase;
    float* xnW = sm + D_XN + warp * (4 * 184);
    float* wW  = sm + D_W  + warp * (4 * 64);

    #pragma unroll
    for (int j = 0; j < 4; ++j) {
        const float* xr = x + (gbase + j) * IDIM;
        float xv[6];
        float s1 = 0.f, s2 = 0.f;
        #pragma unroll
        for (int t = 0; t < 6; ++t) {
            int d = lane + 32 * t;
            float v = (d < IDIM) ? xr[d] : 0.f;
            xv[t] = v; s1 += v; s2 = fmaf(v, v, s2);
        }
        s1 = wsum(s1); s2 = wsum(s2);
        float mu = s1 * (1.0f / IDIM);
        float rs = rsqrtf(s2 * (1.0f / IDIM) - mu * mu + 1e-5f);
        #pragma unroll
        for (int t = 0; t < 6; ++t) {
            int d = lane + 32 * t;
            if (d < IDIM)
                xnW[j * 184 + d] = (xv[t] - mu) * rs * sm[D_G1 + d] + sm[D_B1 + d];
        }
    }
    __syncwarp();

    float a0[4] = {0.f, 0.f, 0.f, 0.f}, a1[4] = {0.f, 0.f, 0.f, 0.f};
    const float* t0p = sm + D_TT + lane * 188;
    const float* t1p = t0p + 32 * 188;
    #pragma unroll 3
    for (int d4 = 0; d4 < IDIM; d4 += 4) {
        float4 t0 = *(const float4*)(t0p + d4);
        float4 t1 = *(const float4*)(t1p + d4);
        #pragma unroll
        for (int j = 0; j < 4; ++j) {
            float4 xv = *(const float4*)(xnW + j * 184 + d4);
            a0[j] = fmaf(xv.x, t0.x, fmaf(xv.y, t0.y, fmaf(xv.z, t0.z, fmaf(xv.w, t0.w, a0[j]))));
            a1[j] = fmaf(xv.x, t1.x, fmaf(xv.y, t1.y, fmaf(xv.z, t1.z, fmaf(xv.w, t1.w, a1[j]))));
        }
    }

    float w1a[4], w2a[4], mu2a[4];
    #pragma unroll
    for (int j = 0; j < 4; ++j) {
        float mx = wmax(fmaxf(a0[j], a1[j]));
        float e1 = __expf(a0[j] - mx), e2 = __expf(a1[j] - mx);
        float sum = wsum(e1 + e2);
        float inv = 1.0f / sum;
        float w1 = e1 * inv, w2 = e2 * inv;
        float* wo = out_w + (gbase + j) * NS;
        wo[lane] = w1; wo[lane + 32] = w2;
        __nv_bfloat16 h1 = __float2bfloat16(w1);
        __nv_bfloat16 h2 = __float2bfloat16(w2);
        long long wb = (gbase + j) * NS;
        g_whi[wb + lane] = h1;
        g_whi[wb + lane + 32] = h2;
        g_wlo[wb + lane] = __float2bfloat16(w1 - __bfloat162float(h1));
        g_wlo[wb + lane + 32] = __float2bfloat16(w2 - __bfloat162float(h2));
        wW[j * 64 + lane] = w1; wW[j * 64 + lane + 32] = w2;
        w1a[j] = w1; w2a[j] = w2;
        mu2a[j] = wsum(w1 * sm[D_M + lane] + w2 * sm[D_M + lane + 32]);
    }
    __syncwarp();

    const float* gr0 = sm + D_G + lane * 65;
    const float* gr1 = gr0 + 32 * 65;
    #pragma unroll
    for (int j = 0; j < 4; ++j) {
        float gw1 = 0.f, gw2 = 0.f;
        #pragma unroll 4
        for (int sp = 0; sp < NS; ++sp) {
            float ws = wW[j * 64 + sp];
            gw1 = fmaf(gr0[sp], ws, gw1);
            gw2 = fmaf(gr1[sp], ws, gw2);
        }
        float ssq = wsum(w1a[j] * gw1 + w2a[j] * gw2);
        float mu2 = mu2a[j];
        float rs2 = rsqrtf(ssq * (1.0f / SDIM) - mu2 * mu2 + 1e-5f);
        if (lane == 0) {
            g_stats[gbase + j] = mu2;
            g_stats[(long long)NB * NI + gbase + j] = rs2;
        }
    }
}

// ---------------- mma.sync output GEMM: s = LN(w @ slots) -------------------
// Tile: 128 i x 128 d per block, K = NS = 64 fully resident (R6-proven layout).
#define OM_SWHI 0
#define OM_SWLO 18432
#define OM_SSHI 36864
#define OM_SSLO 55296
#define OM_MU   73728
#define OM_RS   74240
#define OM_GAM  74752
#define OM_BET  75264
#define OM_BYTES 75776

__global__ void __launch_bounds__(256) out_mma_kernel(
    const float* __restrict__ g2v, const float* __restrict__ b2v,
    float* __restrict__ out_s)
{
    extern __shared__ char smc[];
    int tid = threadIdx.x;
    int b = blockIdx.z;
    int i0 = blockIdx.y * 128;
    int d0 = blockIdx.x * 128;
    long long gib = (long long)b * NI + i0;

    const uint4* wh = (const uint4*)(g_whi + gib * NS);
    const uint4* wl = (const uint4*)(g_wlo + gib * NS);
    const uint4* sh = (const uint4*)(g_sThi + ((long long)b * SDIM + d0) * NS);
    const uint4* sl = (const uint4*)(g_sTlo + ((long long)b * SDIM + d0) * NS);
    #pragma unroll
    for (int it = 0; it < 4; ++it) {
        int idx = tid + 256 * it;            // 1024 uint4 per operand
        int r = idx >> 3, q = idx & 7;
        uint32_t doff = (uint32_t)r * 144 + (uint32_t)q * 16;
        *(uint4*)(smc + OM_SWHI + doff) = wh[idx];
        *(uint4*)(smc + OM_SWLO + doff) = wl[idx];
        *(uint4*)(smc + OM_SSHI + doff) = sh[idx];
        *(uint4*)(smc + OM_SSLO + doff) = sl[idx];
    }
    if (tid < 128) {
        ((float*)(smc + OM_MU))[tid]  = g_stats[gib + tid];
        ((float*)(smc + OM_RS))[tid]  = g_stats[(long long)NB * NI + gib + tid];
        ((float*)(smc + OM_GAM))[tid] = g2v[d0 + tid];
        ((float*)(smc + OM_BET))[tid] = b2v[d0 + tid];
    }
    __syncthreads();

    int wid = tid >> 5, lane = tid & 31;
    int wm = wid & 3, wn = wid >> 2;      // warp tile: 32 i x 64 d
    uint32_t sbase = smem_u32(smc);
    int trow = lane & 15;
    uint32_t tcolb = (uint32_t)(lane >> 4) * 16;   // A ldmatrix col byte offset

    float c[2][8][4];
    #pragma unroll
    for (int mi = 0; mi < 2; ++mi)
        #pragma unroll
        for (int nj = 0; nj < 8; ++nj)
            #pragma unroll
            for (int q = 0; q < 4; ++q) c[mi][nj][q] = 0.f;

    uint32_t brow = (uint32_t)(wn * 64 + ((lane >> 3) & 1) * 8 + (lane & 7)) * 144;
    uint32_t bcolbase = (uint32_t)(lane >> 4) * 16;

    #pragma unroll
    for (int ks = 0; ks < 4; ++ks) {
        uint32_t kb = (uint32_t)ks * 32 + tcolb;
        uint32_t ah[2][4], al[2][4];
        #pragma unroll
        for (int mi = 0; mi < 2; ++mi) {
            uint32_t ra = sbase + OM_SWHI + (uint32_t)(wm * 32 + mi * 16 + trow) * 144 + kb;
            ldm_x4(ra, ah[mi]);
            ldm_x4(ra + (OM_SWLO - OM_SWHI), al[mi]);
        }
        uint32_t bcol = (uint32_t)ks * 32 + bcolbase;
        #pragma unroll
        for (int g = 0; g < 4; ++g) {
            uint32_t rb = sbase + OM_SSHI + brow + (uint32_t)(g * 16) * 144 + bcol;
            uint32_t th[4], tl[4];
            ldm_x4(rb, th);
            ldm_x4(rb + (OM_SSLO - OM_SSHI), tl);
            uint32_t bh0[2] = {th[0], th[2]}, bh1[2] = {th[1], th[3]};
            uint32_t bl0[2] = {tl[0], tl[2]}, bl1[2] = {tl[1], tl[3]};
            #pragma unroll
            for (int mi = 0; mi < 2; ++mi) {
                mma_bf16(c[mi][2 * g],     ah[mi], bh0);
                mma_bf16(c[mi][2 * g],     ah[mi], bl0);
                mma_bf16(c[mi][2 * g],     al[mi], bh0);
                mma_bf16(c[mi][2 * g + 1], ah[mi], bh1);
                mma_bf16(c[mi][2 * g + 1], ah[mi], bl1);
                mma_bf16(c[mi][2 * g + 1], al[mi], bh1);
            }
        }
    }

    // epilogue: LN + store
    const float* muP = (const float*)(smc + OM_MU);
    const float* rsP = (const float*)(smc + OM_RS);
    const float* gmP = (const float*)(smc + OM_GAM);
    const float* btP = (const float*)(smc + OM_BET);
    int grp = lane >> 2, tig = lane & 3;
    #pragma unroll
    for (int mi = 0; mi < 2; ++mi) {
        int r0 = wm * 32 + mi * 16 + grp;
        int r1 = r0 + 8;
        float mu0 = muP[r0], rs0 = rsP[r0];
        float mu1 = muP[r1], rs1 = rsP[r1];
        #pragma unroll
        for (int nj = 0; nj < 8; ++nj) {
            int col = wn * 64 + nj * 8 + 2 * tig;
            float2 gm = *(const float2*)(gmP + col);
            float2 bt = *(const float2*)(btP + col);
            float* c4 = c[mi][nj];
            float2 v0, v1;
            v0.x = (c4[0] - mu0) * rs0 * gm.x + bt.x;
            v0.y = (c4[1] - mu0) * rs0 * gm.y + bt.y;
            v1.x = (c4[2] - mu1) * rs1 * gm.x + bt.x;
            v1.y = (c4[3] - mu1) * rs1 * gm.y + bt.y;
            *(float2*)(out_s + (gib + r0) * (long long)SDIM + d0 + col) = v0;
            *(float2*)(out_s + (gib + r1) * (long long)SDIM + d0 + col) = v1;
        }
    }
}

// ------------------------------- launcher -----------------------------------
extern "C" void kernel_launch(void* const* d_in, const int* in_sizes, int n_in,
                              void* d_out, int out_size)
{
    const float* x     = (const float*)d_in[0];
    const float* slots = (const float*)d_in[1];
    const float* Wq    = (const float*)d_in[2];
    const float* Wk    = (const float*)d_in[3];
    const float* g1v   = (const float*)d_in[4];
    const float* b1v   = (const float*)d_in[5];
    const float* g2v   = (const float*)d_in[6];
    const float* b2v   = (const float*)d_in[7];

    float* out_s = (float*)d_out;
    float* out_w = out_s + (long long)NB * NI * SDIM;

    float *pMpart, *pM, *pTpart, *pGpart;
    cudaGetSymbolAddress((void**)&pMpart, g_Mpart);
    cudaGetSymbolAddress((void**)&pM,     g_M);
    cudaGetSymbolAddress((void**)&pTpart, g_Tpart);
    cudaGetSymbolAddress((void**)&pGpart, g_Gpart);

    cudaFuncSetAttribute(dots_kernel, cudaFuncAttributeMaxDynamicSharedMemorySize, DOTS_SMEM_BYTES);
    cudaFuncSetAttribute(out_mma_kernel, cudaFuncAttributeMaxDynamicSharedMemorySize, OM_BYTES);

    float scale = (float)(1.0 / sqrt((double)ADIM));

    // 1) M = Wq @ Wk^T (180 x 1536), split-K x8 (576 blocks)
    gemm_nt<<<dim3(3, 24, 8), 256>>>(Wq, Wk, pMpart, IDIM, ADIM, ADIM / 8,
                                     ADIM, ADIM, 0LL, 0LL, 8);
    // 2) reduce M
    reduce_bt<<<dim3((IDIM * ADIM + 255) / 256, 1), 256>>>(pMpart, pM, IDIM * ADIM, 8);
    // 3) T[b] = M @ slots[b]^T, split-K x16 (384 blocks)
    gemm_nt<<<dim3(3, 1, 128), 256>>>(pM, slots, pTpart, IDIM, NS, SDIM / 16,
                                      ADIM, SDIM, 0LL, (long long)NS * SDIM, 16);
    // 4) G[b] = slots slots^T, split-K x16 (128 blocks)
    gemm_nt<<<dim3(1, 1, 128), 256>>>(slots, slots, pGpart, NS, NS, SDIM / 16,
                                      SDIM, SDIM, (long long)NS * SDIM, (long long)NS * SDIM, 16);
    // 5) fused finishers
    prep_finish<<<592, 256>>>(slots, scale);
    // 6) dots + softmax + LN2 stats (+ w bf16 hi/lo)
    dots_kernel<<<dim3(NI / 32, NB), 256, DOTS_SMEM_BYTES>>>(x, g1v, b1v, out_w);
    // 7) output GEMM + LN epilogue (R6 configuration)
    out_mma_kernel<<<dim3(SDIM / 128, NI / 128, NB), 256, OM_BYTES>>>(g2v, b2v, out_s);
}

// round 9
// speedup vs baseline: 1.2578x; 1.0583x over previous
#include <cuda_runtime.h>
#include <cuda_bf16.h>
#include <cstdint>
#include <cmath>

typedef unsigned long long ull;

#define NB   8
#define NI   8192
#define IDIM 180
#define ADIM 1536
#define SDIM 1536
#define NS   64

// ----------------------------- device scratch -------------------------------
__device__ float g_Mpart[8 * IDIM * ADIM];
__device__ float g_M[IDIM * ADIM];
__device__ float g_Tpart[128 * IDIM * NS];
__device__ float g_Tt[NB * NS * IDIM];
__device__ float g_Gpart[128 * NS * NS];
__device__ float g_G[NB * NS * NS];
__device__ float g_m[NB * NS];
__device__ float g_stats[2 * NB * NI];
__device__ __align__(16) __nv_bfloat16 g_sThi[NB * SDIM * NS];   // slots^T hi [b][d][s]
__device__ __align__(16) __nv_bfloat16 g_sTlo[NB * SDIM * NS];   // slots^T lo
__device__ __align__(16) __nv_bfloat16 g_whi[NB * NI * NS];      // w hi [b][i][s]
__device__ __align__(16) __nv_bfloat16 g_wlo[NB * NI * NS];      // w lo

// ----------------------------- warp helpers ---------------------------------
__device__ __forceinline__ float wsum(float v) {
    #pragma unroll
    for (int o = 16; o > 0; o >>= 1) v += __shfl_xor_sync(0xffffffffu, v, o);
    return v;
}
__device__ __forceinline__ float wmax(float v) {
    #pragma unroll
    for (int o = 16; o > 0; o >>= 1) v = fmaxf(v, __shfl_xor_sync(0xffffffffu, v, o));
    return v;
}
__device__ __forceinline__ uint32_t smem_u32(const void* p) {
    uint32_t a;
    asm("{ .reg .u64 t; cvta.to.shared.u64 t, %1; cvt.u32.u64 %0, t; }" : "=r"(a) : "l"(p));
    return a;
}

// --------------------------- mma.sync helpers --------------------------------
__device__ __forceinline__ void ldm_x4(uint32_t a, uint32_t* r) {
    asm volatile("ldmatrix.sync.aligned.m8n8.x4.shared.b16 {%0,%1,%2,%3}, [%4];"
        : "=r"(r[0]), "=r"(r[1]), "=r"(r[2]), "=r"(r[3]) : "r"(a));
}
__device__ __forceinline__ void mma_bf16(float* c, const uint32_t* a, const uint32_t* b) {
    asm volatile("mma.sync.aligned.m16n8k16.row.col.f32.bf16.bf16.f32 "
        "{%0,%1,%2,%3}, {%4,%5,%6,%7}, {%8,%9}, {%0,%1,%2,%3};"
        : "+f"(c[0]), "+f"(c[1]), "+f"(c[2]), "+f"(c[3])
        : "r"(a[0]), "r"(a[1]), "r"(a[2]), "r"(a[3]), "r"(b[0]), "r"(b[1]));
}

// ----------------------- shared GEMM tile body (NT) --------------------------
__device__ __forceinline__ void gemm_body(
    const float* __restrict__ A, const float* __restrict__ B, float* __restrict__ Cp,
    int M, int N, int Kchunk, int lda, int ldb, int m0, int n0,
    float (*As)[68], float (*Bs)[68])
{
    int tid = threadIdx.x;
    int tr = tid >> 4, tc = tid & 15;
    int lr = tid >> 2, lq = tid & 3;

    float acc[4][4] = {};

    for (int kb = 0; kb < Kchunk; kb += 16) {
        __syncthreads();
        float4 av = make_float4(0.f, 0.f, 0.f, 0.f);
        if (m0 + lr < M)
            av = *(const float4*)&A[(long long)(m0 + lr) * lda + kb + 4 * lq];
        As[4 * lq + 0][lr] = av.x; As[4 * lq + 1][lr] = av.y;
        As[4 * lq + 2][lr] = av.z; As[4 * lq + 3][lr] = av.w;
        float4 bv = make_float4(0.f, 0.f, 0.f, 0.f);
        if (n0 + lr < N)
            bv = *(const float4*)&B[(long long)(n0 + lr) * ldb + kb + 4 * lq];
        Bs[4 * lq + 0][lr] = bv.x; Bs[4 * lq + 1][lr] = bv.y;
        Bs[4 * lq + 2][lr] = bv.z; Bs[4 * lq + 3][lr] = bv.w;
        __syncthreads();
        #pragma unroll
        for (int k = 0; k < 16; ++k) {
            float4 a4 = *(const float4*)&As[k][4 * tr];
            float4 b4 = *(const float4*)&Bs[k][4 * tc];
            float a[4] = {a4.x, a4.y, a4.z, a4.w};
            float b[4] = {b4.x, b4.y, b4.z, b4.w};
            #pragma unroll
            for (int i = 0; i < 4; ++i)
                #pragma unroll
                for (int j = 0; j < 4; ++j)
                    acc[i][j] = fmaf(a[i], b[j], acc[i][j]);
        }
    }
    #pragma unroll
    for (int i = 0; i < 4; ++i)
        #pragma unroll
        for (int j = 0; j < 4; ++j) {
            int m = m0 + 4 * tr + i, n = n0 + 4 * tc + j;
            if (m < M && n < N) Cp[(long long)m * N + n] = acc[i][j];
        }
}

// ------------- fused M + G partial GEMMs (independent, one launch) ----------
// blocks [0,576): M = Wq @ Wk^T split-K x8;  [576,704): G[b] = slots slots^T x16
__global__ void __launch_bounds__(256) gemm_MG(
    const float* __restrict__ Wq, const float* __restrict__ Wk,
    const float* __restrict__ slots)
{
    __shared__ __align__(16) float As[16][68];
    __shared__ __align__(16) float Bs[16][68];
    int bx = blockIdx.x;
    if (bx < 576) {
        int kk = bx & 7;
        int rem = bx >> 3;
        int mx = rem % 3, ny = rem / 3;
        gemm_body(Wq + kk * (ADIM / 8), Wk + kk * (ADIM / 8),
                  g_Mpart + (long long)kk * IDIM * ADIM,
                  IDIM, ADIM, ADIM / 8, ADIM, ADIM, mx * 64, ny * 64, As, Bs);
    } else {
        int z = bx - 576;
        int kk = z & 15, b = z >> 4;
        const float* sb = slots + (long long)b * NS * SDIM + kk * (SDIM / 16);
        gemm_body(sb, sb, g_Gpart + (long long)z * NS * NS,
                  NS, NS, SDIM / 16, SDIM, SDIM, 0, 0, As, Bs);
    }
}

// -------------------- T[b] = M @ slots^T, split-K x16 -----------------------
__global__ void __launch_bounds__(256) gemm_T(const float* __restrict__ slots)
{
    __shared__ __align__(16) float As[16][68];
    __shared__ __align__(16) float Bs[16][68];
    int z = blockIdx.z;
    int kk = z & 15, b = z >> 4;
    gemm_body(g_M + kk * (SDIM / 16),
              slots + (long long)b * NS * SDIM + kk * (SDIM / 16),
              g_Tpart + (long long)z * IDIM * NS,
              IDIM, NS, SDIM / 16, ADIM, SDIM, blockIdx.x * 64, 0, As, Bs);
}

// -------------------------- split-K reduce for M ----------------------------
__global__ void reduce_bt(const float* __restrict__ part, float* __restrict__ out,
                          int nper, int nparts)
{
    int b = blockIdx.y;
    int i = blockIdx.x * 256 + threadIdx.x;
    if (i >= nper) return;
    const float* p = part + (long long)b * nparts * nper + i;
    float s = 0.f;
    for (int k = 0; k < nparts; ++k) s += p[(long long)k * nper];
    out[(long long)b * nper + i] = s;
}

// ---------------- fused finisher: reduce_G + reduce_T + means + split -------
__global__ void __launch_bounds__(256) prep_finish(const float* __restrict__ slots,
                                                   float scale)
{
    __shared__ float ts[64][129];
    int bx = blockIdx.x;
    int tid = threadIdx.x;

    if (bx < 128) {                       // reduce G (16 parts per batch)
        int idx = bx * 256 + tid;
        int b = idx >> 12, r = idx & 4095;
        const float* p = g_Gpart + ((long long)b * 16) * (NS * NS) + r;
        float s = 0.f;
        #pragma unroll
        for (int k = 0; k < 16; ++k) s += p[(long long)k * (NS * NS)];
        g_G[(long long)b * (NS * NS) + r] = s;
    } else if (bx < 488) {                // reduce T (16 parts; + scale + transpose)
        int idx = (bx - 128) * 256 + tid;
        if (idx < 8 * IDIM * NS) {
            int b = idx / (IDIM * NS);
            int i = idx % (IDIM * NS);
            int s = i / IDIM, d = i % IDIM;
            const float* p = g_Tpart + ((long long)b * 16) * (IDIM * NS) + d * NS + s;
            float acc = 0.f;
            #pragma unroll
            for (int k = 0; k < 16; ++k) acc += p[(long long)k * (IDIM * NS)];
            g_Tt[(long long)b * (NS * IDIM) + i] = acc * scale;
        }
    } else if (bx < 496) {                // slot means
        int b = bx - 488;
        int warp = tid >> 5, lane = tid & 31;
        for (int s = warp; s < NS; s += 8) {
            const float* r = slots + ((long long)b * NS + s) * SDIM;
            float acc = 0.f;
            for (int d = lane; d < SDIM; d += 32) acc += r[d];
            acc = wsum(acc);
            if (lane == 0) g_m[b * NS + s] = acc * (1.0f / SDIM);
        }
    } else {                              // split slots -> sT hi/lo
        int jd = bx - 496;
        int b = jd / 12;
        int d0 = (jd % 12) * 128;
        for (int idx = tid; idx < 64 * 128; idx += 256) {
            int s = idx >> 7, dd = idx & 127;
            ts[s][dd] = slots[((long long)b * NS + s) * SDIM + d0 + dd];
        }
        __syncthreads();
        for (int idx = tid; idx < 128 * 64; idx += 256) {
            int d = idx >> 6, s = idx & 63;
            float v = ts[s][d];
            __nv_bfloat16 h = __float2bfloat16(v);
            __nv_bfloat16 l = __float2bfloat16(v - __bfloat162float(h));
            long long o = ((long long)b * SDIM + d0 + d) * NS + s;
            g_sThi[o] = h;
            g_sTlo[o] = l;
        }
    }
}

// ----------------- dots + softmax + LN2-stats fused kernel ------------------
// Now 128 rows per block (4 passes of 32 rows) to amortize the Tt/G preload.
#define D_TT   0            // 64 x 188
#define D_G    12032        // 64 x 65
#define D_M    16192        // 64
#define D_G1   16256        // 184
#define D_B1   16440        // 184
#define D_XN   16624        // 8 warps x 4 rows x 184
#define D_W    22512        // 8 warps x 4 rows x 64
#define DOTS_SMEM_FLOATS 24560
#define DOTS_SMEM_BYTES  (DOTS_SMEM_FLOATS * 4)

__global__ void __launch_bounds__(256) dots_kernel(
    const float* __restrict__ x, const float* __restrict__ g1v,
    const float* __restrict__ b1v, float* __restrict__ out_w)
{
    extern __shared__ float sm[];
    int tid = threadIdx.x;
    int b = blockIdx.y;

    for (int i = tid; i < IDIM * NS; i += 256) {
        int s = i / IDIM, d = i % IDIM;
        sm[D_TT + s * 188 + d] = g_Tt[(long long)b * (NS * IDIM) + i];
    }
    for (int i = tid; i < NS * NS; i += 256) {
        int s = i >> 6, c = i & 63;
        sm[D_G + s * 65 + c] = g_G[(long long)b * (NS * NS) + i];
    }
    if (tid < NS) sm[D_M + tid] = g_m[b * NS + tid];
    if (tid < IDIM) { sm[D_G1 + tid] = g1v[tid]; sm[D_B1 + tid] = b1v[tid]; }
    __syncthreads();

    int warp = tid >> 5, lane = tid & 31;
    float* xnW = sm + D_XN + warp * (4 * 184);
    float* wW  = sm + D_W  + warp * (4 * 64);
    const float* t0p = sm + D_TT + lane * 188;
    const float* t1p = t0p + 32 * 188;
    const float* gr0 = sm + D_G + lane * 65;
    const float* gr1 = gr0 + 32 * 65;

    for (int pass = 0; pass < 4; ++pass) {
        long long rowbase = (long long)blockIdx.x * 128 + pass * 32 + warp * 4;
        long long gbase = (long long)b * NI + rowbase;

        #pragma unroll
        for (int j = 0; j < 4; ++j) {
            const float* xr = x + (gbase + j) * IDIM;
            float xv[6];
            float s1 = 0.f, s2 = 0.f;
            #pragma unroll
            for (int t = 0; t < 6; ++t) {
                int d = lane + 32 * t;
                float v = (d < IDIM) ? xr[d] : 0.f;
                xv[t] = v; s1 += v; s2 = fmaf(v, v, s2);
            }
            s1 = wsum(s1); s2 = wsum(s2);
            float mu = s1 * (1.0f / IDIM);
            float rs = rsqrtf(s2 * (1.0f / IDIM) - mu * mu + 1e-5f);
            #pragma unroll
            for (int t = 0; t < 6; ++t) {
                int d = lane + 32 * t;
                if (d < IDIM)
                    xnW[j * 184 + d] = (xv[t] - mu) * rs * sm[D_G1 + d] + sm[D_B1 + d];
            }
        }
        __syncwarp();

        float a0[4] = {0.f, 0.f, 0.f, 0.f}, a1[4] = {0.f, 0.f, 0.f, 0.f};
        #pragma unroll 3
        for (int d4 = 0; d4 < IDIM; d4 += 4) {
            float4 t0 = *(const float4*)(t0p + d4);
            float4 t1 = *(const float4*)(t1p + d4);
            #pragma unroll
            for (int j = 0; j < 4; ++j) {
                float4 xv = *(const float4*)(xnW + j * 184 + d4);
                a0[j] = fmaf(xv.x, t0.x, fmaf(xv.y, t0.y, fmaf(xv.z, t0.z, fmaf(xv.w, t0.w, a0[j]))));
                a1[j] = fmaf(xv.x, t1.x, fmaf(xv.y, t1.y, fmaf(xv.z, t1.z, fmaf(xv.w, t1.w, a1[j]))));
            }
        }

        float w1a[4], w2a[4], mu2a[4];
        #pragma unroll
        for (int j = 0; j < 4; ++j) {
            float mx = wmax(fmaxf(a0[j], a1[j]));
            float e1 = __expf(a0[j] - mx), e2 = __expf(a1[j] - mx);
            float sum = wsum(e1 + e2);
            float inv = 1.0f / sum;
            float w1 = e1 * inv, w2 = e2 * inv;
            float* wo = out_w + (gbase + j) * NS;
            wo[lane] = w1; wo[lane + 32] = w2;
            __nv_bfloat16 h1 = __float2bfloat16(w1);
            __nv_bfloat16 h2 = __float2bfloat16(w2);
            long long wb = (gbase + j) * NS;
            g_whi[wb + lane] = h1;
            g_whi[wb + lane + 32] = h2;
            g_wlo[wb + lane] = __float2bfloat16(w1 - __bfloat162float(h1));
            g_wlo[wb + lane + 32] = __float2bfloat16(w2 - __bfloat162float(h2));
            wW[j * 64 + lane] = w1; wW[j * 64 + lane + 32] = w2;
            w1a[j] = w1; w2a[j] = w2;
            mu2a[j] = wsum(w1 * sm[D_M + lane] + w2 * sm[D_M + lane + 32]);
        }
        __syncwarp();

        #pragma unroll
        for (int j = 0; j < 4; ++j) {
            float gw1 = 0.f, gw2 = 0.f;
            #pragma unroll 4
            for (int sp = 0; sp < NS; ++sp) {
                float ws = wW[j * 64 + sp];
                gw1 = fmaf(gr0[sp], ws, gw1);
                gw2 = fmaf(gr1[sp], ws, gw2);
            }
            float ssq = wsum(w1a[j] * gw1 + w2a[j] * gw2);
            float mu2 = mu2a[j];
            float rs2 = rsqrtf(ssq * (1.0f / SDIM) - mu2 * mu2 + 1e-5f);
            if (lane == 0) {
                g_stats[gbase + j] = mu2;
                g_stats[(long long)NB * NI + gbase + j] = rs2;
            }
        }
        __syncwarp();
    }
}

// ---------------- mma.sync output GEMM: s = LN(w @ slots) -------------------
// Tile: 128 i x 128 d per block, K = NS = 64 fully resident (R6-proven layout).
#define OM_SWHI 0
#define OM_SWLO 18432
#define OM_SSHI 36864
#define OM_SSLO 55296
#define OM_MU   73728
#define OM_RS   74240
#define OM_GAM  74752
#define OM_BET  75264
#define OM_BYTES 75776

__global__ void __launch_bounds__(256) out_mma_kernel(
    const float* __restrict__ g2v, const float* __restrict__ b2v,
    float* __restrict__ out_s)
{
    extern __shared__ char smc[];
    int tid = threadIdx.x;
    int b = blockIdx.z;
    int i0 = blockIdx.y * 128;
    int d0 = blockIdx.x * 128;
    long long gib = (long long)b * NI + i0;

    const uint4* wh = (const uint4*)(g_whi + gib * NS);
    const uint4* wl = (const uint4*)(g_wlo + gib * NS);
    const uint4* sh = (const uint4*)(g_sThi + ((long long)b * SDIM + d0) * NS);
    const uint4* sl = (const uint4*)(g_sTlo + ((long long)b * SDIM + d0) * NS);
    #pragma unroll
    for (int it = 0; it < 4; ++it) {
        int idx = tid + 256 * it;
        int r = idx >> 3, q = idx & 7;
        uint32_t doff = (uint32_t)r * 144 + (uint32_t)q * 16;
        *(uint4*)(smc + OM_SWHI + doff) = wh[idx];
        *(uint4*)(smc + OM_SWLO + doff) = wl[idx];
        *(uint4*)(smc + OM_SSHI + doff) = sh[idx];
        *(uint4*)(smc + OM_SSLO + doff) = sl[idx];
    }
    if (tid < 128) {
        ((float*)(smc + OM_MU))[tid]  = g_stats[gib + tid];
        ((float*)(smc + OM_RS))[tid]  = g_stats[(long long)NB * NI + gib + tid];
        ((float*)(smc + OM_GAM))[tid] = g2v[d0 + tid];
        ((float*)(smc + OM_BET))[tid] = b2v[d0 + tid];
    }
    __syncthreads();

    int wid = tid >> 5, lane = tid & 31;
    int wm = wid & 3, wn = wid >> 2;
    uint32_t sbase = smem_u32(smc);
    int trow = lane & 15;
    uint32_t tcolb = (uint32_t)(lane >> 4) * 16;

    float c[2][8][4];
    #pragma unroll
    for (int mi = 0; mi < 2; ++mi)
        #pragma unroll
        for (int nj = 0; nj < 8; ++nj)
            #pragma unroll
            for (int q = 0; q < 4; ++q) c[mi][nj][q] = 0.f;

    uint32_t brow = (uint32_t)(wn * 64 + ((lane >> 3) & 1) * 8 + (lane & 7)) * 144;
    uint32_t bcolbase = (uint32_t)(lane >> 4) * 16;

    #pragma unroll
    for (int ks = 0; ks < 4; ++ks) {
        uint32_t kb = (uint32_t)ks * 32 + tcolb;
        uint32_t ah[2][4], al[2][4];
        #pragma unroll
        for (int mi = 0; mi < 2; ++mi) {
            uint32_t ra = sbase + OM_SWHI + (uint32_t)(wm * 32 + mi * 16 + trow) * 144 + kb;
            ldm_x4(ra, ah[mi]);
            ldm_x4(ra + (OM_SWLO - OM_SWHI), al[mi]);
        }
        uint32_t bcol = (uint32_t)ks * 32 + bcolbase;
        #pragma unroll
        for (int g = 0; g < 4; ++g) {
            uint32_t rb = sbase + OM_SSHI + brow + (uint32_t)(g * 16) * 144 + bcol;
            uint32_t th[4], tl[4];
            ldm_x4(rb, th);
            ldm_x4(rb + (OM_SSLO - OM_SSHI), tl);
            uint32_t bh0[2] = {th[0], th[2]}, bh1[2] = {th[1], th[3]};
            uint32_t bl0[2] = {tl[0], tl[2]}, bl1[2] = {tl[1], tl[3]};
            #pragma unroll
            for (int mi = 0; mi < 2; ++mi) {
                mma_bf16(c[mi][2 * g],     ah[mi], bh0);
                mma_bf16(c[mi][2 * g],     ah[mi], bl0);
                mma_bf16(c[mi][2 * g],     al[mi], bh0);
                mma_bf16(c[mi][2 * g + 1], ah[mi], bh1);
                mma_bf16(c[mi][2 * g + 1], ah[mi], bl1);
                mma_bf16(c[mi][2 * g + 1], al[mi], bh1);
            }
        }
    }

    const float* muP = (const float*)(smc + OM_MU);
    const float* rsP = (const float*)(smc + OM_RS);
    const float* gmP = (const float*)(smc + OM_GAM);
    const float* btP = (const float*)(smc + OM_BET);
    int grp = lane >> 2, tig = lane & 3;
    #pragma unroll
    for (int mi = 0; mi < 2; ++mi) {
        int r0 = wm * 32 + mi * 16 + grp;
        int r1 = r0 + 8;
        float mu0 = muP[r0], rs0 = rsP[r0];
        float mu1 = muP[r1], rs1 = rsP[r1];
        #pragma unroll
        for (int nj = 0; nj < 8; ++nj) {
            int col = wn * 64 + nj * 8 + 2 * tig;
            float2 gm = *(const float2*)(gmP + col);
            float2 bt = *(const float2*)(btP + col);
            float* c4 = c[mi][nj];
            float2 v0, v1;
            v0.x = (c4[0] - mu0) * rs0 * gm.x + bt.x;
            v0.y = (c4[1] - mu0) * rs0 * gm.y + bt.y;
            v1.x = (c4[2] - mu1) * rs1 * gm.x + bt.x;
            v1.y = (c4[3] - mu1) * rs1 * gm.y + bt.y;
            *(float2*)(out_s + (gib + r0) * (long long)SDIM + d0 + col) = v0;
            *(float2*)(out_s + (gib + r1) * (long long)SDIM + d0 + col) = v1;
        }
    }
}

// ------------------------------- launcher -----------------------------------
extern "C" void kernel_launch(void* const* d_in, const int* in_sizes, int n_in,
                              void* d_out, int out_size)
{
    const float* x     = (const float*)d_in[0];
    const float* slots = (const float*)d_in[1];
    const float* Wq    = (const float*)d_in[2];
    const float* Wk    = (const float*)d_in[3];
    const float* g1v   = (const float*)d_in[4];
    const float* b1v   = (const float*)d_in[5];
    const float* g2v   = (const float*)d_in[6];
    const float* b2v   = (const float*)d_in[7];

    float* out_s = (float*)d_out;
    float* out_w = out_s + (long long)NB * NI * SDIM;

    float *pMpart, *pM;
    cudaGetSymbolAddress((void**)&pMpart, g_Mpart);
    cudaGetSymbolAddress((void**)&pM,     g_M);

    cudaFuncSetAttribute(dots_kernel, cudaFuncAttributeMaxDynamicSharedMemorySize, DOTS_SMEM_BYTES);
    cudaFuncSetAttribute(out_mma_kernel, cudaFuncAttributeMaxDynamicSharedMemorySize, OM_BYTES);

    float scale = (float)(1.0 / sqrt((double)ADIM));

    // 1) fused: M = Wq @ Wk^T (x8 split)  ||  G[b] = slots slots^T (x16 split)
    gemm_MG<<<704, 256>>>(Wq, Wk, slots);
    // 2) reduce M
    reduce_bt<<<dim3((IDIM * ADIM + 255) / 256, 1), 256>>>(pMpart, pM, IDIM * ADIM, 8);
    // 3) T[b] = M @ slots[b]^T, split-K x16
    gemm_T<<<dim3(3, 1, 128), 256>>>(slots);
    // 4) fused finishers: reduce G, reduce+scale+transpose T, slot means, split slots
    prep_finish<<<592, 256>>>(slots, scale);
    // 5) dots + softmax + LN2 stats (+ w bf16 hi/lo), 128 rows/block
    dots_kernel<<<dim3(NI / 128, NB), 256, DOTS_SMEM_BYTES>>>(x, g1v, b1v, out_w);
    // 6) output GEMM + LN epilogue
    out_mma_kernel<<<dim3(SDIM / 128, NI / 128, NB), 256, OM_BYTES>>>(g2v, b2v, out_s);
}

// round 10
// speedup vs baseline: 1.2993x; 1.0330x over previous
#include <cuda_runtime.h>
#include <cuda_bf16.h>
#include <cstdint>
#include <cmath>

typedef unsigned long long ull;

#define NB   8
#define NI   8192
#define IDIM 180
#define ADIM 1536
#define SDIM 1536
#define NS   64

// ----------------------------- device scratch -------------------------------
__device__ float g_Mpart[8 * IDIM * ADIM];
__device__ float g_M[IDIM * ADIM];
__device__ float g_Tpart[128 * IDIM * NS];
__device__ float g_Tt[NB * NS * IDIM];
__device__ float g_Gpart[128 * NS * NS];
__device__ float g_G[NB * NS * NS];
__device__ float g_m[NB * NS];
__device__ float g_stats[2 * NB * NI];
__device__ __align__(16) __nv_bfloat16 g_sThi[NB * SDIM * NS];   // slots^T hi [b][d][s]
__device__ __align__(16) __nv_bfloat16 g_sTlo[NB * SDIM * NS];   // slots^T lo
__device__ __align__(16) __nv_bfloat16 g_whi[NB * NI * NS];      // w hi [b][i][s]
__device__ __align__(16) __nv_bfloat16 g_wlo[NB * NI * NS];      // w lo

// ----------------------------- warp helpers ---------------------------------
__device__ __forceinline__ float wsum(float v) {
    #pragma unroll
    for (int o = 16; o > 0; o >>= 1) v += __shfl_xor_sync(0xffffffffu, v, o);
    return v;
}
__device__ __forceinline__ float wmax(float v) {
    #pragma unroll
    for (int o = 16; o > 0; o >>= 1) v = fmaxf(v, __shfl_xor_sync(0xffffffffu, v, o));
    return v;
}
__device__ __forceinline__ uint32_t smem_u32(const void* p) {
    uint32_t a;
    asm("{ .reg .u64 t; cvta.to.shared.u64 t, %1; cvt.u32.u64 %0, t; }" : "=r"(a) : "l"(p));
    return a;
}

// ----------------------------- f32x2 helpers ---------------------------------
__device__ __forceinline__ ull fma2(ull a, ull b, ull c) {
    ull d;
    asm("fma.rn.f32x2 %0, %1, %2, %3;" : "=l"(d) : "l"(a), "l"(b), "l"(c));
    return d;
}
__device__ __forceinline__ float2 unpack2(ull u) {
    float lo, hi;
    asm("mov.b64 {%0, %1}, %2;" : "=f"(lo), "=f"(hi) : "l"(u));
    return make_float2(lo, hi);
}

// --------------------------- mma.sync helpers --------------------------------
__device__ __forceinline__ void ldm_x4(uint32_t a, uint32_t* r) {
    asm volatile("ldmatrix.sync.aligned.m8n8.x4.shared.b16 {%0,%1,%2,%3}, [%4];"
        : "=r"(r[0]), "=r"(r[1]), "=r"(r[2]), "=r"(r[3]) : "r"(a));
}
__device__ __forceinline__ void mma_bf16(float* c, const uint32_t* a, const uint32_t* b) {
    asm volatile("mma.sync.aligned.m16n8k16.row.col.f32.bf16.bf16.f32 "
        "{%0,%1,%2,%3}, {%4,%5,%6,%7}, {%8,%9}, {%0,%1,%2,%3};"
        : "+f"(c[0]), "+f"(c[1]), "+f"(c[2]), "+f"(c[3])
        : "r"(a[0]), "r"(a[1]), "r"(a[2]), "r"(a[3]), "r"(b[0]), "r"(b[1]));
}

// ----------------------- shared GEMM tile body (NT) --------------------------
__device__ __forceinline__ void gemm_body(
    const float* __restrict__ A, const float* __restrict__ B, float* __restrict__ Cp,
    int M, int N, int Kchunk, int lda, int ldb, int m0, int n0,
    float (*As)[68], float (*Bs)[68])
{
    int tid = threadIdx.x;
    int tr = tid >> 4, tc = tid & 15;
    int lr = tid >> 2, lq = tid & 3;

    float acc[4][4] = {};

    for (int kb = 0; kb < Kchunk; kb += 16) {
        __syncthreads();
        float4 av = make_float4(0.f, 0.f, 0.f, 0.f);
        if (m0 + lr < M)
            av = *(const float4*)&A[(long long)(m0 + lr) * lda + kb + 4 * lq];
        As[4 * lq + 0][lr] = av.x; As[4 * lq + 1][lr] = av.y;
        As[4 * lq + 2][lr] = av.z; As[4 * lq + 3][lr] = av.w;
        float4 bv = make_float4(0.f, 0.f, 0.f, 0.f);
        if (n0 + lr < N)
            bv = *(const float4*)&B[(long long)(n0 + lr) * ldb + kb + 4 * lq];
        Bs[4 * lq + 0][lr] = bv.x; Bs[4 * lq + 1][lr] = bv.y;
        Bs[4 * lq + 2][lr] = bv.z; Bs[4 * lq + 3][lr] = bv.w;
        __syncthreads();
        #pragma unroll
        for (int k = 0; k < 16; ++k) {
            float4 a4 = *(const float4*)&As[k][4 * tr];
            float4 b4 = *(const float4*)&Bs[k][4 * tc];
            float a[4] = {a4.x, a4.y, a4.z, a4.w};
            float b[4] = {b4.x, b4.y, b4.z, b4.w};
            #pragma unroll
            for (int i = 0; i < 4; ++i)
                #pragma unroll
                for (int j = 0; j < 4; ++j)
                    acc[i][j] = fmaf(a[i], b[j], acc[i][j]);
        }
    }
    #pragma unroll
    for (int i = 0; i < 4; ++i)
        #pragma unroll
        for (int j = 0; j < 4; ++j) {
            int m = m0 + 4 * tr + i, n = n0 + 4 * tc + j;
            if (m < M && n < N) Cp[(long long)m * N + n] = acc[i][j];
        }
}

// ------------- fused M + G partial GEMMs (independent, one launch) ----------
__global__ void __launch_bounds__(256) gemm_MG(
    const float* __restrict__ Wq, const float* __restrict__ Wk,
    const float* __restrict__ slots)
{
    __shared__ __align__(16) float As[16][68];
    __shared__ __align__(16) float Bs[16][68];
    int bx = blockIdx.x;
    if (bx < 576) {
        int kk = bx & 7;
        int rem = bx >> 3;
        int mx = rem % 3, ny = rem / 3;
        gemm_body(Wq + kk * (ADIM / 8), Wk + kk * (ADIM / 8),
                  g_Mpart + (long long)kk * IDIM * ADIM,
                  IDIM, ADIM, ADIM / 8, ADIM, ADIM, mx * 64, ny * 64, As, Bs);
    } else {
        int z = bx - 576;
        int kk = z & 15, b = z >> 4;
        const float* sb = slots + (long long)b * NS * SDIM + kk * (SDIM / 16);
        gemm_body(sb, sb, g_Gpart + (long long)z * NS * NS,
                  NS, NS, SDIM / 16, SDIM, SDIM, 0, 0, As, Bs);
    }
}

// -------------------- T[b] = M @ slots^T, split-K x16 -----------------------
__global__ void __launch_bounds__(256) gemm_T(const float* __restrict__ slots)
{
    __shared__ __align__(16) float As[16][68];
    __shared__ __align__(16) float Bs[16][68];
    int z = blockIdx.z;
    int kk = z & 15, b = z >> 4;
    gemm_body(g_M + kk * (SDIM / 16),
              slots + (long long)b * NS * SDIM + kk * (SDIM / 16),
              g_Tpart + (long long)z * IDIM * NS,
              IDIM, NS, SDIM / 16, ADIM, SDIM, blockIdx.x * 64, 0, As, Bs);
}

// -------------------------- split-K reduce for M ----------------------------
__global__ void reduce_bt(const float* __restrict__ part, float* __restrict__ out,
                          int nper, int nparts)
{
    int b = blockIdx.y;
    int i = blockIdx.x * 256 + threadIdx.x;
    if (i >= nper) return;
    const float* p = part + (long long)b * nparts * nper + i;
    float s = 0.f;
    for (int k = 0; k < nparts; ++k) s += p[(long long)k * nper];
    out[(long long)b * nper + i] = s;
}

// ---------------- fused finisher: reduce_G + reduce_T + means + split -------
// blocks: [0,128) reduce G, [128,152) reduce T (coalesced+transpose),
//         [152,160) slot means, [160,256) split slots
__global__ void __launch_bounds__(256) prep_finish(const float* __restrict__ slots,
                                                   float scale)
{
    __shared__ float ts[64][129];
    int bx = blockIdx.x;
    int tid = threadIdx.x;

    if (bx < 128) {                       // reduce G (coalesced)
        int idx = bx * 256 + tid;
        int b = idx >> 12, r = idx & 4095;
        const float* p = g_Gpart + ((long long)b * 16) * (NS * NS) + r;
        float s = 0.f;
        #pragma unroll
        for (int k = 0; k < 16; ++k) s += p[(long long)k * (NS * NS)];
        g_G[(long long)b * (NS * NS) + r] = s;
    } else if (bx < 152) {                // reduce T: coalesced reads + smem transpose
        int z = bx - 128;
        int b = z / 3, dg = z % 3;
        int dbase = dg * 64;
        int dcount = (dbase + 64 <= IDIM) ? 64 : (IDIM - dbase);   // 64,64,52
        const float* p = g_Tpart + (long long)b * 16 * (IDIM * NS) + (long long)dbase * NS;
        int nelem = dcount * NS;
        for (int e = 0; e < 16; ++e) {
            int idx = tid + 256 * e;
            if (idx < nelem) {
                float acc = 0.f;
                #pragma unroll
                for (int k = 0; k < 16; ++k) acc += p[(long long)k * (IDIM * NS) + idx];
                int dl = idx >> 6, s = idx & 63;
                ts[s][dl] = acc * scale;
            }
        }
        __syncthreads();
        float* outp = g_Tt + (long long)b * (NS * IDIM) + dbase;
        for (int o = tid; o < 64 * 64; o += 256) {
            int s = o >> 6, dl = o & 63;
            if (dl < dcount) outp[(long long)s * IDIM + dl] = ts[s][dl];
        }
    } else if (bx < 160) {                // slot means
        int b = bx - 152;
        int warp = tid >> 5, lane = tid & 31;
        for (int s = warp; s < NS; s += 8) {
            const float* r = slots + ((long long)b * NS + s) * SDIM;
            float acc = 0.f;
            for (int d = lane; d < SDIM; d += 32) acc += r[d];
            acc = wsum(acc);
            if (lane == 0) g_m[b * NS + s] = acc * (1.0f / SDIM);
        }
    } else {                              // split slots -> sT hi/lo
        int jd = bx - 160;
        int b = jd / 12;
        int d0 = (jd % 12) * 128;
        for (int idx = tid; idx < 64 * 128; idx += 256) {
            int s = idx >> 7, dd = idx & 127;
            ts[s][dd] = slots[((long long)b * NS + s) * SDIM + d0 + dd];
        }
        __syncthreads();
        for (int idx = tid; idx < 128 * 64; idx += 256) {
            int d = idx >> 6, s = idx & 63;
            float v = ts[s][d];
            __nv_bfloat16 h = __float2bfloat16(v);
            __nv_bfloat16 l = __float2bfloat16(v - __bfloat162float(h));
            long long o = ((long long)b * SDIM + d0 + d) * NS + s;
            g_sThi[o] = h;
            g_sTlo[o] = l;
        }
    }
}

// ----------------- dots + softmax + LN2-stats fused kernel ------------------
// 128 rows per block (4 passes of 32); f32x2 packed FMA in dot phases.
#define D_TT   0            // 64 x 188
#define D_G    12032        // 64 x 68
#define D_M    16384        // 64
#define D_G1   16448        // 184
#define D_B1   16632        // 184
#define D_XN   16816        // 8 warps x 4 rows x 184
#define D_W    22704        // 8 warps x 4 rows x 64
#define DOTS_SMEM_FLOATS 24752
#define DOTS_SMEM_BYTES  (DOTS_SMEM_FLOATS * 4)

__global__ void __launch_bounds__(256) dots_kernel(
    const float* __restrict__ x, const float* __restrict__ g1v,
    const float* __restrict__ b1v, float* __restrict__ out_w)
{
    extern __shared__ float sm[];
    int tid = threadIdx.x;
    int b = blockIdx.y;

    for (int i = tid; i < IDIM * NS; i += 256) {
        int s = i / IDIM, d = i % IDIM;
        sm[D_TT + s * 188 + d] = g_Tt[(long long)b * (NS * IDIM) + i];
    }
    for (int i = tid; i < NS * NS; i += 256) {
        int s = i >> 6, c = i & 63;
        sm[D_G + s * 68 + c] = g_G[(long long)b * (NS * NS) + i];
    }
    if (tid < NS) sm[D_M + tid] = g_m[b * NS + tid];
    if (tid < IDIM) { sm[D_G1 + tid] = g1v[tid]; sm[D_B1 + tid] = b1v[tid]; }
    __syncthreads();

    int warp = tid >> 5, lane = tid & 31;
    float* xnW = sm + D_XN + warp * (4 * 184);
    float* wW  = sm + D_W  + warp * (4 * 64);
    const float* t0p = sm + D_TT + lane * 188;
    const float* t1p = t0p + 32 * 188;
    const float* gr0 = sm + D_G + lane * 68;
    const float* gr1 = gr0 + 32 * 68;

    for (int pass = 0; pass < 4; ++pass) {
        long long rowbase = (long long)blockIdx.x * 128 + pass * 32 + warp * 4;
        long long gbase = (long long)b * NI + rowbase;

        #pragma unroll
        for (int j = 0; j < 4; ++j) {
            const float* xr = x + (gbase + j) * IDIM;
            float xv[6];
            float s1 = 0.f, s2 = 0.f;
            #pragma unroll
            for (int t = 0; t < 6; ++t) {
                int d = lane + 32 * t;
                float v = (d < IDIM) ? xr[d] : 0.f;
                xv[t] = v; s1 += v; s2 = fmaf(v, v, s2);
            }
            s1 = wsum(s1); s2 = wsum(s2);
            float mu = s1 * (1.0f / IDIM);
            float rs = rsqrtf(s2 * (1.0f / IDIM) - mu * mu + 1e-5f);
            #pragma unroll
            for (int t = 0; t < 6; ++t) {
                int d = lane + 32 * t;
                if (d < IDIM)
                    xnW[j * 184 + d] = (xv[t] - mu) * rs * sm[D_G1 + d] + sm[D_B1 + d];
            }
        }
        __syncwarp();

        // dots: packed f32x2 FMA (2x fp32 throughput)
        ull A0[4] = {0, 0, 0, 0}, A1[4] = {0, 0, 0, 0};
        #pragma unroll 3
        for (int d4 = 0; d4 < IDIM; d4 += 4) {
            ulonglong2 t0 = *(const ulonglong2*)(t0p + d4);
            ulonglong2 t1 = *(const ulonglong2*)(t1p + d4);
            #pragma unroll
            for (int j = 0; j < 4; ++j) {
                ulonglong2 xv = *(const ulonglong2*)(xnW + j * 184 + d4);
                A0[j] = fma2(xv.x, t0.x, A0[j]);
                A0[j] = fma2(xv.y, t0.y, A0[j]);
                A1[j] = fma2(xv.x, t1.x, A1[j]);
                A1[j] = fma2(xv.y, t1.y, A1[j]);
            }
        }
        float a0[4], a1[4];
        #pragma unroll
        for (int j = 0; j < 4; ++j) {
            float2 q0 = unpack2(A0[j]), q1 = unpack2(A1[j]);
            a0[j] = q0.x + q0.y;
            a1[j] = q1.x + q1.y;
        }

        float w1a[4], w2a[4], mu2a[4];
        #pragma unroll
        for (int j = 0; j < 4; ++j) {
            float mx = wmax(fmaxf(a0[j], a1[j]));
            float e1 = __expf(a0[j] - mx), e2 = __expf(a1[j] - mx);
            float sum = wsum(e1 + e2);
            float inv = 1.0f / sum;
            float w1 = e1 * inv, w2 = e2 * inv;
            float* wo = out_w + (gbase + j) * NS;
            wo[lane] = w1; wo[lane + 32] = w2;
            __nv_bfloat16 h1 = __float2bfloat16(w1);
            __nv_bfloat16 h2 = __float2bfloat16(w2);
            long long wb = (gbase + j) * NS;
            g_whi[wb + lane] = h1;
            g_whi[wb + lane + 32] = h2;
            g_wlo[wb + lane] = __float2bfloat16(w1 - __bfloat162float(h1));
            g_wlo[wb + lane + 32] = __float2bfloat16(w2 - __bfloat162float(h2));
            wW[j * 64 + lane] = w1; wW[j * 64 + lane + 32] = w2;
            w1a[j] = w1; w2a[j] = w2;
            mu2a[j] = wsum(w1 * sm[D_M + lane] + w2 * sm[D_M + lane + 32]);
        }
        __syncwarp();

        #pragma unroll
        for (int j = 0; j < 4; ++j) {
            ull GW1 = 0, GW2 = 0;
            #pragma unroll 4
            for (int sp = 0; sp < NS; sp += 4) {
                ulonglong2 wv = *(const ulonglong2*)(wW + j * 64 + sp);
                ulonglong2 q0 = *(const ulonglong2*)(gr0 + sp);
                ulonglong2 q1 = *(const ulonglong2*)(gr1 + sp);
                GW1 = fma2(q0.x, wv.x, GW1);
                GW1 = fma2(q0.y, wv.y, GW1);
                GW2 = fma2(q1.x, wv.x, GW2);
                GW2 = fma2(q1.y, wv.y, GW2);
            }
            float2 p1 = unpack2(GW1), p2 = unpack2(GW2);
            float gw1 = p1.x + p1.y, gw2 = p2.x + p2.y;
            float ssq = wsum(w1a[j] * gw1 + w2a[j] * gw2);
            float mu2 = mu2a[j];
            float rs2 = rsqrtf(ssq * (1.0f / SDIM) - mu2 * mu2 + 1e-5f);
            if (lane == 0) {
                g_stats[gbase + j] = mu2;
                g_stats[(long long)NB * NI + gbase + j] = rs2;
            }
        }
        __syncwarp();
    }
}

// ---------------- mma.sync output GEMM: s = LN(w @ slots) -------------------
#define OM_SWHI 0
#define OM_SWLO 18432
#define OM_SSHI 36864
#define OM_SSLO 55296
#define OM_MU   73728
#define OM_RS   74240
#define OM_GAM  74752
#define OM_BET  75264
#define OM_BYTES 75776

__global__ void __launch_bounds__(256) out_mma_kernel(
    const float* __restrict__ g2v, const float* __restrict__ b2v,
    float* __restrict__ out_s)
{
    extern __shared__ char smc[];
    int tid = threadIdx.x;
    int b = blockIdx.z;
    int i0 = blockIdx.y * 128;
    int d0 = blockIdx.x * 128;
    long long gib = (long long)b * NI + i0;

    const uint4* wh = (const uint4*)(g_whi + gib * NS);
    const uint4* wl = (const uint4*)(g_wlo + gib * NS);
    const uint4* sh = (const uint4*)(g_sThi + ((long long)b * SDIM + d0) * NS);
    const uint4* sl = (const uint4*)(g_sTlo + ((long long)b * SDIM + d0) * NS);
    #pragma unroll
    for (int it = 0; it < 4; ++it) {
        int idx = tid + 256 * it;
        int r = idx >> 3, q = idx & 7;
        uint32_t doff = (uint32_t)r * 144 + (uint32_t)q * 16;
        *(uint4*)(smc + OM_SWHI + doff) = wh[idx];
        *(uint4*)(smc + OM_SWLO + doff) = wl[idx];
        *(uint4*)(smc + OM_SSHI + doff) = sh[idx];
        *(uint4*)(smc + OM_SSLO + doff) = sl[idx];
    }
    if (tid < 128) {
        ((float*)(smc + OM_MU))[tid]  = g_stats[gib + tid];
        ((float*)(smc + OM_RS))[tid]  = g_stats[(long long)NB * NI + gib + tid];
        ((float*)(smc + OM_GAM))[tid] = g2v[d0 + tid];
        ((float*)(smc + OM_BET))[tid] = b2v[d0 + tid];
    }
    __syncthreads();

    int wid = tid >> 5, lane = tid & 31;
    int wm = wid & 3, wn = wid >> 2;
    uint32_t sbase = smem_u32(smc);
    int trow = lane & 15;
    uint32_t tcolb = (uint32_t)(lane >> 4) * 16;

    float c[2][8][4];
    #pragma unroll
    for (int mi = 0; mi < 2; ++mi)
        #pragma unroll
        for (int nj = 0; nj < 8; ++nj)
            #pragma unroll
            for (int q = 0; q < 4; ++q) c[mi][nj][q] = 0.f;

    uint32_t brow = (uint32_t)(wn * 64 + ((lane >> 3) & 1) * 8 + (lane & 7)) * 144;
    uint32_t bcolbase = (uint32_t)(lane >> 4) * 16;

    #pragma unroll
    for (int ks = 0; ks < 4; ++ks) {
        uint32_t kb = (uint32_t)ks * 32 + tcolb;
        uint32_t ah[2][4], al[2][4];
        #pragma unroll
        for (int mi = 0; mi < 2; ++mi) {
            uint32_t ra = sbase + OM_SWHI + (uint32_t)(wm * 32 + mi * 16 + trow) * 144 + kb;
            ldm_x4(ra, ah[mi]);
            ldm_x4(ra + (OM_SWLO - OM_SWHI), al[mi]);
        }
        uint32_t bcol = (uint32_t)ks * 32 + bcolbase;
        #pragma unroll
        for (int g = 0; g < 4; ++g) {
            uint32_t rb = sbase + OM_SSHI + brow + (uint32_t)(g * 16) * 144 + bcol;
            uint32_t th[4], tl[4];
            ldm_x4(rb, th);
            ldm_x4(rb + (OM_SSLO - OM_SSHI), tl);
            uint32_t bh0[2] = {th[0], th[2]}, bh1[2] = {th[1], th[3]};
            uint32_t bl0[2] = {tl[0], tl[2]}, bl1[2] = {tl[1], tl[3]};
            #pragma unroll
            for (int mi = 0; mi < 2; ++mi) {
                mma_bf16(c[mi][2 * g],     ah[mi], bh0);
                mma_bf16(c[mi][2 * g],     ah[mi], bl0);
                mma_bf16(c[mi][2 * g],     al[mi], bh0);
                mma_bf16(c[mi][2 * g + 1], ah[mi], bh1);
                mma_bf16(c[mi][2 * g + 1], ah[mi], bl1);
                mma_bf16(c[mi][2 * g + 1], al[mi], bh1);
            }
        }
    }

    const float* muP = (const float*)(smc + OM_MU);
    const float* rsP = (const float*)(smc + OM_RS);
    const float* gmP = (const float*)(smc + OM_GAM);
    const float* btP = (const float*)(smc + OM_BET);
    int grp = lane >> 2, tig = lane & 3;
    #pragma unroll
    for (int mi = 0; mi < 2; ++mi) {
        int r0 = wm * 32 + mi * 16 + grp;
        int r1 = r0 + 8;
        float mu0 = muP[r0], rs0 = rsP[r0];
        float mu1 = muP[r1], rs1 = rsP[r1];
        #pragma unroll
        for (int nj = 0; nj < 8; ++nj) {
            int col = wn * 64 + nj * 8 + 2 * tig;
            float2 gm = *(const float2*)(gmP + col);
            float2 bt = *(const float2*)(btP + col);
            float* c4 = c[mi][nj];
            float2 v0, v1;
            v0.x = (c4[0] - mu0) * rs0 * gm.x + bt.x;
            v0.y = (c4[1] - mu0) * rs0 * gm.y + bt.y;
            v1.x = (c4[2] - mu1) * rs1 * gm.x + bt.x;
            v1.y = (c4[3] - mu1) * rs1 * gm.y + bt.y;
            *(float2*)(out_s + (gib + r0) * (long long)SDIM + d0 + col) = v0;
            *(float2*)(out_s + (gib + r1) * (long long)SDIM + d0 + col) = v1;
        }
    }
}

// ------------------------------- launcher -----------------------------------
extern "C" void kernel_launch(void* const* d_in, const int* in_sizes, int n_in,
                              void* d_out, int out_size)
{
    const float* x     = (const float*)d_in[0];
    const float* slots = (const float*)d_in[1];
    const float* Wq    = (const float*)d_in[2];
    const float* Wk    = (const float*)d_in[3];
    const float* g1v   = (const float*)d_in[4];
    const float* b1v   = (const float*)d_in[5];
    const float* g2v   = (const float*)d_in[6];
    const float* b2v   = (const float*)d_in[7];

    float* out_s = (float*)d_out;
    float* out_w = out_s + (long long)NB * NI * SDIM;

    float *pMpart, *pM;
    cudaGetSymbolAddress((void**)&pMpart, g_Mpart);
    cudaGetSymbolAddress((void**)&pM,     g_M);

    cudaFuncSetAttribute(dots_kernel, cudaFuncAttributeMaxDynamicSharedMemorySize, DOTS_SMEM_BYTES);
    cudaFuncSetAttribute(out_mma_kernel, cudaFuncAttributeMaxDynamicSharedMemorySize, OM_BYTES);

    float scale = (float)(1.0 / sqrt((double)ADIM));

    // 1) fused: M = Wq @ Wk^T (x8 split)  ||  G[b] = slots slots^T (x16 split)
    gemm_MG<<<704, 256>>>(Wq, Wk, slots);
    // 2) reduce M
    reduce_bt<<<dim3((IDIM * ADIM + 255) / 256, 1), 256>>>(pMpart, pM, IDIM * ADIM, 8);
    // 3) T[b] = M @ slots[b]^T, split-K x16
    gemm_T<<<dim3(3, 1, 128), 256>>>(slots);
    // 4) fused finishers (coalesced T-reduce)
    prep_finish<<<256, 256>>>(slots, scale);
    // 5) dots + softmax + LN2 stats (+ w bf16 hi/lo), 128 rows/block, f32x2
    dots_kernel<<<dim3(NI / 128, NB), 256, DOTS_SMEM_BYTES>>>(x, g1v, b1v, out_w);
    // 6) output GEMM + LN epilogue
    out_mma_kernel<<<dim3(SDIM / 128, NI / 128, NB), 256, OM_BYTES>>>(g2v, b2v, out_s);
}